// round 10
// baseline (speedup 1.0000x reference)
#include <cuda_runtime.h>
#include <cuda_bf16.h>
#include <cstdint>

// ---------------- problem constants ----------------
#define N_STREAMS 8
#define D_MODEL   2048
#define NS        16
#define N_SKEW    120
#define KPAD      128
#define TOKENS    8192

#define TILE_M    64
#define M_TILES   (TOKENS / TILE_M)    // 128
#define KC        64                   // d per chunk
#define NC        (D_MODEL / KC)       // 32 chunks
#define PITCH_B   144                  // row pitch bytes (72 bf16)

#define N_CONS_W  4                    // consumer warps (0..3)
#define N_PROD_T  384                  // producer threads (warps 4..15)

#define A_OFF(buf, hl) (((buf) * 2 + (hl)) * 9216)
#define B_BASE 36864
#define B_OFF(buf, hl) (B_BASE + ((buf) * 2 + (hl)) * 18432)
#define BIAS_OFF (B_BASE + 73728)
#define SMEM_TOTAL (BIAS_OFF + 512)

// ---------------- device scratch ----------------
__device__ __nv_bfloat16 g_Whi[KPAD * D_MODEL];   // 512 KB
__device__ __nv_bfloat16 g_Wlo[KPAD * D_MODEL];   // 512 KB

// ---------------- K0: W -> bf16 hi/lo (padded to 128 rows) ----------------
__global__ void prep_wt_kernel(const float* __restrict__ W) {
    int id = blockIdx.x * 256 + threadIdx.x;
    int k = id >> 11, d = id & (D_MODEL - 1);
    float v = (k < N_SKEW) ? W[k * D_MODEL + d] : 0.f;
    __nv_bfloat16 hi = __float2bfloat16(v);
    __nv_bfloat16 lo = __float2bfloat16(v - __bfloat162float(hi));
    g_Whi[id] = hi;
    g_Wlo[id] = lo;
}

// ---------------- fused kernel ----------------
__device__ __forceinline__ void mma16816(float c[4], const uint32_t a[4],
                                         uint32_t b0, uint32_t b1) {
    asm volatile(
        "mma.sync.aligned.m16n8k16.row.col.f32.bf16.bf16.f32 "
        "{%0,%1,%2,%3}, {%4,%5,%6,%7}, {%8,%9}, {%0,%1,%2,%3};"
        : "+f"(c[0]), "+f"(c[1]), "+f"(c[2]), "+f"(c[3])
        : "r"(a[0]), "r"(a[1]), "r"(a[2]), "r"(a[3]), "r"(b0), "r"(b1));
}

// producer: stage one chunk (A mean hi/lo + B hi/lo) into buffer `buf`
__device__ __forceinline__ void produce_chunk(
    char* smem, const float* __restrict__ streams,
    int tok0, int d0, int buf, int ptid) {
    // A: 64 tokens x 16 slots
    #pragma unroll 1
    for (int idx = ptid; idx < TILE_M * 16; idx += N_PROD_T) {
        int tk   = idx >> 4;
        int slot = idx & 15;
        const float4* src = reinterpret_cast<const float4*>(streams)
            + ((size_t)(tok0 + tk) * N_STREAMS * D_MODEL + d0) / 4 + slot;
        float4 v[N_STREAMS];
        #pragma unroll
        for (int n = 0; n < N_STREAMS; n++) v[n] = src[n * (D_MODEL / 4)];
        #pragma unroll
        for (int s = N_STREAMS / 2; s > 0; s >>= 1)
            #pragma unroll
            for (int n = 0; n < s; n++) {
                v[n].x += v[n+s].x; v[n].y += v[n+s].y;
                v[n].z += v[n+s].z; v[n].w += v[n+s].w;
            }
        float f[4] = { v[0].x*0.125f, v[0].y*0.125f, v[0].z*0.125f, v[0].w*0.125f };
        __nv_bfloat16 hi[4], lo[4];
        #pragma unroll
        for (int i = 0; i < 4; i++) {
            hi[i] = __float2bfloat16(f[i]);
            lo[i] = __float2bfloat16(f[i] - __bfloat162float(hi[i]));
        }
        *reinterpret_cast<uint2*>(smem + A_OFF(buf,0) + tk * PITCH_B + slot * 8) =
            *reinterpret_cast<uint2*>(hi);
        *reinterpret_cast<uint2*>(smem + A_OFF(buf,1) + tk * PITCH_B + slot * 8) =
            *reinterpret_cast<uint2*>(lo);
    }
    // B: 128 rows x 8 quads
    #pragma unroll 1
    for (int idx = ptid; idx < KPAD * 8; idx += N_PROD_T) {
        int r = idx >> 3, q = idx & 7;
        size_t gsrc = (size_t)r * D_MODEL + d0 + q * 8;
        *reinterpret_cast<uint4*>(smem + B_OFF(buf,0) + r * PITCH_B + q * 16) =
            *reinterpret_cast<const uint4*>(&g_Whi[gsrc]);
        *reinterpret_cast<uint4*>(smem + B_OFF(buf,1) + r * PITCH_B + q * 16) =
            *reinterpret_cast<const uint4*>(&g_Wlo[gsrc]);
    }
}

__global__ void __launch_bounds__(512, 1)
gomhc_fused_kernel(const float* __restrict__ streams,
                   const float* __restrict__ bias,
                   float* __restrict__ out) {
    extern __shared__ char smem[];
    const int tid  = threadIdx.x;
    const int wid  = tid >> 5;
    const int lane = tid & 31;
    const int tok0 = blockIdx.x * TILE_M;

    if (tid < KPAD)
        *reinterpret_cast<float*>(smem + BIAS_OFF + tid * 4) =
            (tid < N_SKEW) ? bias[tid] : 0.f;

    const bool producer = (wid >= N_CONS_W);

    // consumer mapping: warp owns all 64 rows x 32 cols (wn)
    const int g  = lane >> 2;
    const int t  = lane & 3;
    const int wn = wid * 32;
    float acc[4][4][4];
    #pragma unroll
    for (int mt = 0; mt < 4; mt++)
        #pragma unroll
        for (int nt = 0; nt < 4; nt++)
            #pragma unroll
            for (int i = 0; i < 4; i++) acc[mt][nt][i] = 0.f;

    if (producer)
        produce_chunk(smem, streams, tok0, 0, 0, tid - N_CONS_W * 32);
    __syncthreads();

    // =================== main loop ===================
    #pragma unroll 1
    for (int c = 0; c < NC; c++) {
        const int buf = c & 1;

        if (producer) {
            if (c + 1 < NC)
                produce_chunk(smem, streams, tok0, (c + 1) * KC,
                              (c + 1) & 1, tid - N_CONS_W * 32);
        } else {
            const char* pah = smem + A_OFF(buf, 0);
            const char* pal = smem + A_OFF(buf, 1);
            const char* pbh = smem + B_OFF(buf, 0);
            const char* pbl = smem + B_OFF(buf, 1);
            #pragma unroll
            for (int ks = 0; ks < 4; ks++) {
                const int kb = ks * 16 + 2 * t;
                // process m-tiles in pairs to cap live registers
                #pragma unroll
                for (int mh = 0; mh < 2; mh++) {
                    uint32_t Ah[2][4], Al[2][4];
                    #pragma unroll
                    for (int m2 = 0; m2 < 2; m2++) {
                        int r0 = (mh * 2 + m2) * 16 + g;
                        Ah[m2][0] = *reinterpret_cast<const uint32_t*>(pah + (r0    ) * PITCH_B + kb * 2);
                        Ah[m2][1] = *reinterpret_cast<const uint32_t*>(pah + (r0 + 8) * PITCH_B + kb * 2);
                        Ah[m2][2] = *reinterpret_cast<const uint32_t*>(pah + (r0    ) * PITCH_B + (kb + 8) * 2);
                        Ah[m2][3] = *reinterpret_cast<const uint32_t*>(pah + (r0 + 8) * PITCH_B + (kb + 8) * 2);
                        Al[m2][0] = *reinterpret_cast<const uint32_t*>(pal + (r0    ) * PITCH_B + kb * 2);
                        Al[m2][1] = *reinterpret_cast<const uint32_t*>(pal + (r0 + 8) * PITCH_B + kb * 2);
                        Al[m2][2] = *reinterpret_cast<const uint32_t*>(pal + (r0    ) * PITCH_B + (kb + 8) * 2);
                        Al[m2][3] = *reinterpret_cast<const uint32_t*>(pal + (r0 + 8) * PITCH_B + (kb + 8) * 2);
                    }
                    #pragma unroll
                    for (int nt = 0; nt < 4; nt++) {
                        int n0 = wn + nt * 8 + g;
                        uint32_t bh0 = *reinterpret_cast<const uint32_t*>(pbh + n0 * PITCH_B + kb * 2);
                        uint32_t bh1 = *reinterpret_cast<const uint32_t*>(pbh + n0 * PITCH_B + (kb + 8) * 2);
                        uint32_t bl0 = *reinterpret_cast<const uint32_t*>(pbl + n0 * PITCH_B + kb * 2);
                        uint32_t bl1 = *reinterpret_cast<const uint32_t*>(pbl + n0 * PITCH_B + (kb + 8) * 2);
                        #pragma unroll
                        for (int m2 = 0; m2 < 2; m2++) {
                            float* a = acc[mh * 2 + m2][nt];
                            mma16816(a, Ah[m2], bh0, bh1);
                            mma16816(a, Ah[m2], bl0, bl1);
                            mma16816(a, Al[m2], bh0, bh1);
                        }
                    }
                }
            }
        }
        __syncthreads();
    }

    // =================== epilogue: z -> smem (alias over A region) ===================
    float* zs = reinterpret_cast<float*>(smem);    // [64][128]
    if (!producer) {
        #pragma unroll
        for (int mt = 0; mt < 4; mt++)
            #pragma unroll
            for (int nt = 0; nt < 4; nt++) {
                int row = mt * 16 + g;
                int col = wn + nt * 8 + 2 * t;
                *reinterpret_cast<float2*>(&zs[row * KPAD + col]) =
                    make_float2(acc[mt][nt][0], acc[mt][nt][1]);
                *reinterpret_cast<float2*>(&zs[(row + 8) * KPAD + col]) =
                    make_float2(acc[mt][nt][2], acc[mt][nt][3]);
            }
    }
    __syncthreads();

    // =================== solve: 16 warps x 2 passes x 2 tokens ===================
    {
        const float* bs = reinterpret_cast<const float*>(smem + BIAS_OFF);
        const int half = lane >> 4;
        const int r    = lane & 15;
        const unsigned mask = 0xffffffffu;

        #pragma unroll 1
        for (int pass = 0; pass < 2; pass++) {
            const int tk = wid * 4 + pass * 2 + half;   // 0..63
            const float* zt = zs + tk * KPAD;

            float m[32];
            #pragma unroll
            for (int cc = 0; cc < NS; cc++) {
                float a = 0.f;
                if (cc > r) {
                    int u = (r * (31 - r)) / 2 + (cc - r - 1);
                    a = zt[u] + bs[u];
                } else if (cc < r) {
                    int u = (cc * (31 - cc)) / 2 + (r - cc - 1);
                    a = -(zt[u] + bs[u]);
                }
                float diag = (cc == r) ? 1.f : 0.f;
                m[cc]      = diag + a;
                m[16 + cc] = diag - a;
            }

            #pragma unroll
            for (int i = 0; i < NS; i++) {
                const int src = i + (half << 4);
                float pivi = __shfl_sync(mask, m[i], src);
                float rp = 1.0f / pivi;
                float cf = (r == i) ? (1.0f - rp) : m[i] * rp;
                #pragma unroll
                for (int k = 0; k < 32; k++) {
                    float pk = __shfl_sync(mask, m[k], src);
                    m[k] = fmaf(-cf, pk, m[k]);
                }
            }

            float hq[8];
            #pragma unroll
            for (int q = 0; q < 8; q++) {
                float q0 = m[16 + 2 * q], q1 = m[16 + 2 * q + 1];
                hq[q] = q0 * q0 + q1 * q1;
            }
            #pragma unroll
            for (int q = 0; q < 8; q++)
                hq[q] += __shfl_xor_sync(mask, hq[q], 1);

            if (!(r & 1)) {
                const int tok = tok0 + tk;
                float* o = out + (size_t)tok * 64 + (r >> 1) * 8;
                #pragma unroll
                for (int q = 0; q < 8; q++) o[q] = 0.5f * hq[q];
            }
        }
    }
}

// ---------------- launch ----------------
extern "C" void kernel_launch(void* const* d_in, const int* in_sizes, int n_in,
                              void* d_out, int out_size) {
    const float* streams = (const float*)d_in[0];
    const float* W       = (const float*)d_in[1];
    const float* b       = (const float*)d_in[2];
    float* out = (float*)d_out;

    prep_wt_kernel<<<(KPAD * D_MODEL) / 256, 256>>>(W);

    cudaFuncSetAttribute(gomhc_fused_kernel,
                         cudaFuncAttributeMaxDynamicSharedMemorySize, SMEM_TOTAL);
    gomhc_fused_kernel<<<M_TILES, 512, SMEM_TOTAL>>>(streams, b, out);
}

// round 12
// speedup vs baseline: 1.3048x; 1.3048x over previous
#include <cuda_runtime.h>
#include <cuda_bf16.h>
#include <cstdint>

// ---------------- problem constants ----------------
#define N_STREAMS 8
#define D_MODEL   2048
#define NS        16
#define N_SKEW    120
#define KPAD      128
#define TOKENS    8192

#define TILE_M    64
#define M_TILES   (TOKENS / TILE_M)    // 128
#define KC        64                   // d per chunk
#define NC        (D_MODEL / KC)       // 32 chunks
#define PITCH_B   144                  // row pitch bytes (72 bf16)

#define A_OFF(buf, hl) (((buf) * 2 + (hl)) * 9216)
#define B_BASE 36864
#define B_OFF(buf, hl) (B_BASE + ((buf) * 2 + (hl)) * 18432)
#define BIAS_OFF (B_BASE + 73728)
#define SMEM_TOTAL (BIAS_OFF + 512)

// ---------------- device scratch ----------------
__device__ __nv_bfloat16 g_Whi[KPAD * D_MODEL];   // 512 KB
__device__ __nv_bfloat16 g_Wlo[KPAD * D_MODEL];   // 512 KB

// ---------------- K0: W -> bf16 hi/lo (padded to 128 rows) ----------------
__global__ void prep_wt_kernel(const float* __restrict__ W) {
    int id = blockIdx.x * 256 + threadIdx.x;
    int k = id >> 11, d = id & (D_MODEL - 1);
    float v = (k < N_SKEW) ? W[k * D_MODEL + d] : 0.f;
    __nv_bfloat16 hi = __float2bfloat16(v);
    __nv_bfloat16 lo = __float2bfloat16(v - __bfloat162float(hi));
    g_Whi[id] = hi;
    g_Wlo[id] = lo;
}

// ---------------- fused kernel ----------------
__device__ __forceinline__ void mma16816(float c[4], const uint32_t a[4],
                                         uint32_t b0, uint32_t b1) {
    asm volatile(
        "mma.sync.aligned.m16n8k16.row.col.f32.bf16.bf16.f32 "
        "{%0,%1,%2,%3}, {%4,%5,%6,%7}, {%8,%9}, {%0,%1,%2,%3};"
        : "+f"(c[0]), "+f"(c[1]), "+f"(c[2]), "+f"(c[3])
        : "r"(a[0]), "r"(a[1]), "r"(a[2]), "r"(a[3]), "r"(b0), "r"(b1));
}

// producer: stage one chunk into buffer buf; ptid in [0,256)
// Pairs processed 2-at-a-time with all 16 LDG.128 issued before reduction.
__device__ __forceinline__ void produce_chunk(
    char* smem, const float* __restrict__ streams,
    int tok0, int d0, int buf, int ptid) {
    #pragma unroll
    for (int ph = 0; ph < 2; ph++) {
        int idx0  = ptid + (2 * ph) * 256;
        int idx1  = idx0 + 256;
        int tk0i  = idx0 >> 4, sl0 = idx0 & 15;
        int tk1i  = idx1 >> 4, sl1 = idx1 & 15;
        const float4* s0 = reinterpret_cast<const float4*>(streams)
            + ((size_t)(tok0 + tk0i) * N_STREAMS * D_MODEL + d0) / 4 + sl0;
        const float4* s1 = reinterpret_cast<const float4*>(streams)
            + ((size_t)(tok0 + tk1i) * N_STREAMS * D_MODEL + d0) / 4 + sl1;
        float4 v[N_STREAMS], u[N_STREAMS];
        #pragma unroll
        for (int n = 0; n < N_STREAMS; n++) {
            v[n] = s0[n * (D_MODEL / 4)];
            u[n] = s1[n * (D_MODEL / 4)];
        }
        #pragma unroll
        for (int s = N_STREAMS / 2; s > 0; s >>= 1)
            #pragma unroll
            for (int n = 0; n < s; n++) {
                v[n].x += v[n+s].x; v[n].y += v[n+s].y;
                v[n].z += v[n+s].z; v[n].w += v[n+s].w;
                u[n].x += u[n+s].x; u[n].y += u[n+s].y;
                u[n].z += u[n+s].z; u[n].w += u[n+s].w;
            }
        float f0[4] = { v[0].x*0.125f, v[0].y*0.125f, v[0].z*0.125f, v[0].w*0.125f };
        float f1[4] = { u[0].x*0.125f, u[0].y*0.125f, u[0].z*0.125f, u[0].w*0.125f };
        __nv_bfloat16 h0[4], l0[4], h1[4], l1[4];
        #pragma unroll
        for (int i = 0; i < 4; i++) {
            h0[i] = __float2bfloat16(f0[i]);
            l0[i] = __float2bfloat16(f0[i] - __bfloat162float(h0[i]));
            h1[i] = __float2bfloat16(f1[i]);
            l1[i] = __float2bfloat16(f1[i] - __bfloat162float(h1[i]));
        }
        *reinterpret_cast<uint2*>(smem + A_OFF(buf,0) + tk0i * PITCH_B + sl0 * 8) =
            *reinterpret_cast<uint2*>(h0);
        *reinterpret_cast<uint2*>(smem + A_OFF(buf,1) + tk0i * PITCH_B + sl0 * 8) =
            *reinterpret_cast<uint2*>(l0);
        *reinterpret_cast<uint2*>(smem + A_OFF(buf,0) + tk1i * PITCH_B + sl1 * 8) =
            *reinterpret_cast<uint2*>(h1);
        *reinterpret_cast<uint2*>(smem + A_OFF(buf,1) + tk1i * PITCH_B + sl1 * 8) =
            *reinterpret_cast<uint2*>(l1);
    }
    // B: 128 rows x 8 quads, 4 per thread (fully unrolled, 8 LDG in flight)
    #pragma unroll
    for (int p = 0; p < 4; p++) {
        int idx = ptid + p * 256;
        int r = idx >> 3, q = idx & 7;
        size_t gsrc = (size_t)r * D_MODEL + d0 + q * 8;
        *reinterpret_cast<uint4*>(smem + B_OFF(buf,0) + r * PITCH_B + q * 16) =
            *reinterpret_cast<const uint4*>(&g_Whi[gsrc]);
        *reinterpret_cast<uint4*>(smem + B_OFF(buf,1) + r * PITCH_B + q * 16) =
            *reinterpret_cast<const uint4*>(&g_Wlo[gsrc]);
    }
}

__global__ void __launch_bounds__(512, 1)
gomhc_fused_kernel(const float* __restrict__ streams,
                   const float* __restrict__ bias,
                   float* __restrict__ out) {
    extern __shared__ char smem[];
    const int tid  = threadIdx.x;
    const int wid  = tid >> 5;
    const int lane = tid & 31;
    const int tok0 = blockIdx.x * TILE_M;

    if (tid < KPAD)
        *reinterpret_cast<float*>(smem + BIAS_OFF + tid * 4) =
            (tid < N_SKEW) ? bias[tid] : 0.f;

    const bool producer = (wid >= 8);

    // consumer mapping: 8 warps, wm = (wid&1)*32, wn = (wid>>1)*32
    const int g  = lane >> 2;
    const int t  = lane & 3;
    const int wm = (wid & 1) * 32;
    const int wn = (wid >> 1) * 32;
    float acc[2][4][4];
    #pragma unroll
    for (int mt = 0; mt < 2; mt++)
        #pragma unroll
        for (int nt = 0; nt < 4; nt++)
            #pragma unroll
            for (int i = 0; i < 4; i++) acc[mt][nt][i] = 0.f;

    if (producer)
        produce_chunk(smem, streams, tok0, 0, 0, tid - 256);
    __syncthreads();

    // =================== main loop ===================
    #pragma unroll 1
    for (int c = 0; c < NC; c++) {
        const int buf = c & 1;

        if (producer) {
            if (c + 1 < NC)
                produce_chunk(smem, streams, tok0, (c + 1) * KC,
                              (c + 1) & 1, tid - 256);
        } else {
            const char* pah = smem + A_OFF(buf, 0);
            const char* pal = smem + A_OFF(buf, 1);
            const char* pbh = smem + B_OFF(buf, 0);
            const char* pbl = smem + B_OFF(buf, 1);
            #pragma unroll
            for (int ks = 0; ks < 4; ks++) {
                const int kb = ks * 16 + 2 * t;
                uint32_t Ah[2][4], Al[2][4];
                #pragma unroll
                for (int mt = 0; mt < 2; mt++) {
                    int r0 = wm + mt * 16 + g;
                    Ah[mt][0] = *reinterpret_cast<const uint32_t*>(pah + (r0    ) * PITCH_B + kb * 2);
                    Ah[mt][1] = *reinterpret_cast<const uint32_t*>(pah + (r0 + 8) * PITCH_B + kb * 2);
                    Ah[mt][2] = *reinterpret_cast<const uint32_t*>(pah + (r0    ) * PITCH_B + (kb + 8) * 2);
                    Ah[mt][3] = *reinterpret_cast<const uint32_t*>(pah + (r0 + 8) * PITCH_B + (kb + 8) * 2);
                    Al[mt][0] = *reinterpret_cast<const uint32_t*>(pal + (r0    ) * PITCH_B + kb * 2);
                    Al[mt][1] = *reinterpret_cast<const uint32_t*>(pal + (r0 + 8) * PITCH_B + kb * 2);
                    Al[mt][2] = *reinterpret_cast<const uint32_t*>(pal + (r0    ) * PITCH_B + (kb + 8) * 2);
                    Al[mt][3] = *reinterpret_cast<const uint32_t*>(pal + (r0 + 8) * PITCH_B + (kb + 8) * 2);
                }
                #pragma unroll
                for (int nt = 0; nt < 4; nt++) {
                    int n0 = wn + nt * 8 + g;
                    uint32_t bh0 = *reinterpret_cast<const uint32_t*>(pbh + n0 * PITCH_B + kb * 2);
                    uint32_t bh1 = *reinterpret_cast<const uint32_t*>(pbh + n0 * PITCH_B + (kb + 8) * 2);
                    uint32_t bl0 = *reinterpret_cast<const uint32_t*>(pbl + n0 * PITCH_B + kb * 2);
                    uint32_t bl1 = *reinterpret_cast<const uint32_t*>(pbl + n0 * PITCH_B + (kb + 8) * 2);
                    #pragma unroll
                    for (int mt = 0; mt < 2; mt++) {
                        mma16816(acc[mt][nt], Ah[mt], bh0, bh1);
                        mma16816(acc[mt][nt], Ah[mt], bl0, bl1);
                        mma16816(acc[mt][nt], Al[mt], bh0, bh1);
                    }
                }
            }
        }
        __syncthreads();
    }

    // =================== epilogue: z -> smem (alias over A region) ===================
    float* zs = reinterpret_cast<float*>(smem);    // [64][128]
    if (!producer) {
        #pragma unroll
        for (int mt = 0; mt < 2; mt++)
            #pragma unroll
            for (int nt = 0; nt < 4; nt++) {
                int row = wm + mt * 16 + g;
                int col = wn + nt * 8 + 2 * t;
                *reinterpret_cast<float2*>(&zs[row * KPAD + col]) =
                    make_float2(acc[mt][nt][0], acc[mt][nt][1]);
                *reinterpret_cast<float2*>(&zs[(row + 8) * KPAD + col]) =
                    make_float2(acc[mt][nt][2], acc[mt][nt][3]);
            }
    }
    __syncthreads();

    // =================== solve: 16 warps x 2 passes x 2 tokens ===================
    {
        const float* bs = reinterpret_cast<const float*>(smem + BIAS_OFF);
        const int half = lane >> 4;
        const int r    = lane & 15;
        const unsigned mask = 0xffffffffu;

        #pragma unroll 1
        for (int pass = 0; pass < 2; pass++) {
            const int tk = wid * 4 + pass * 2 + half;   // 0..63
            const float* zt = zs + tk * KPAD;

            float m[32];
            #pragma unroll
            for (int cc = 0; cc < NS; cc++) {
                float a = 0.f;
                if (cc > r) {
                    int u = (r * (31 - r)) / 2 + (cc - r - 1);
                    a = zt[u] + bs[u];
                } else if (cc < r) {
                    int u = (cc * (31 - cc)) / 2 + (r - cc - 1);
                    a = -(zt[u] + bs[u]);
                }
                float diag = (cc == r) ? 1.f : 0.f;
                m[cc]      = diag + a;
                m[16 + cc] = diag - a;
            }

            #pragma unroll
            for (int i = 0; i < NS; i++) {
                const int src = i + (half << 4);
                float pivi = __shfl_sync(mask, m[i], src);
                float rp = 1.0f / pivi;
                float cf = (r == i) ? (1.0f - rp) : m[i] * rp;
                #pragma unroll
                for (int k = 0; k < 32; k++) {
                    float pk = __shfl_sync(mask, m[k], src);
                    m[k] = fmaf(-cf, pk, m[k]);
                }
            }

            float hq[8];
            #pragma unroll
            for (int q = 0; q < 8; q++) {
                float q0 = m[16 + 2 * q], q1 = m[16 + 2 * q + 1];
                hq[q] = q0 * q0 + q1 * q1;
            }
            #pragma unroll
            for (int q = 0; q < 8; q++)
                hq[q] += __shfl_xor_sync(mask, hq[q], 1);

            if (!(r & 1)) {
                const int tok = tok0 + tk;
                float* o = out + (size_t)tok * 64 + (r >> 1) * 8;
                #pragma unroll
                for (int q = 0; q < 8; q++) o[q] = 0.5f * hq[q];
            }
        }
    }
}

// ---------------- launch ----------------
extern "C" void kernel_launch(void* const* d_in, const int* in_sizes, int n_in,
                              void* d_out, int out_size) {
    const float* streams = (const float*)d_in[0];
    const float* W       = (const float*)d_in[1];
    const float* b       = (const float*)d_in[2];
    float* out = (float*)d_out;

    prep_wt_kernel<<<(KPAD * D_MODEL) / 256, 256>>>(W);

    cudaFuncSetAttribute(gomhc_fused_kernel,
                         cudaFuncAttributeMaxDynamicSharedMemorySize, SMEM_TOTAL);
    gomhc_fused_kernel<<<M_TILES, 512, SMEM_TOTAL>>>(streams, b, out);
}

// round 13
// speedup vs baseline: 1.3754x; 1.0541x over previous
#include <cuda_runtime.h>
#include <cuda_bf16.h>
#include <cstdint>

// ---------------- problem constants ----------------
#define N_STREAMS 8
#define D_MODEL   2048
#define NS        16
#define N_SKEW    120
#define KPAD      128
#define TOKENS    8192

#define TILE_M    32
#define M_TILES   (TOKENS / TILE_M)    // 256
#define KC        64                   // d per chunk
#define NC        (D_MODEL / KC)       // 32 chunks
#define PITCH_B   144                  // row pitch bytes (72 bf16)

#define THREADS   256
#define N_PROD_T  128                  // producer threads (warps 4..7)

// smem layout (bytes)
#define A_OFF(buf, hl) (((buf) * 2 + (hl)) * 4608)          // 32 rows * 144
#define B_BASE 18432
#define B_OFF(buf, hl) (B_BASE + ((buf) * 2 + (hl)) * 18432) // 128 rows * 144
#define BIAS_OFF (B_BASE + 73728)                            // = 92160
#define SMEM_TOTAL (BIAS_OFF + 512)                          // 92672

// ---------------- device scratch ----------------
__device__ __nv_bfloat16 g_Whi[KPAD * D_MODEL];   // 512 KB
__device__ __nv_bfloat16 g_Wlo[KPAD * D_MODEL];   // 512 KB

// ---------------- K0: W -> bf16 hi/lo (padded to 128 rows) ----------------
__global__ void prep_wt_kernel(const float* __restrict__ W) {
    int id = blockIdx.x * 256 + threadIdx.x;
    int k = id >> 11, d = id & (D_MODEL - 1);
    float v = (k < N_SKEW) ? W[k * D_MODEL + d] : 0.f;
    __nv_bfloat16 hi = __float2bfloat16(v);
    __nv_bfloat16 lo = __float2bfloat16(v - __bfloat162float(hi));
    g_Whi[id] = hi;
    g_Wlo[id] = lo;
}

// ---------------- fused kernel ----------------
__device__ __forceinline__ void mma16816(float c[4], const uint32_t a[4],
                                         uint32_t b0, uint32_t b1) {
    asm volatile(
        "mma.sync.aligned.m16n8k16.row.col.f32.bf16.bf16.f32 "
        "{%0,%1,%2,%3}, {%4,%5,%6,%7}, {%8,%9}, {%0,%1,%2,%3};"
        : "+f"(c[0]), "+f"(c[1]), "+f"(c[2]), "+f"(c[3])
        : "r"(a[0]), "r"(a[1]), "r"(a[2]), "r"(a[3]), "r"(b0), "r"(b1));
}

// producer: stage one chunk into buffer buf; ptid in [0,128)
// A slots: 32 tokens x 16 slots = 512; 4 per thread, processed 2-at-a-time
// with all 16 LDG.128 issued before reduction.
__device__ __forceinline__ void produce_chunk(
    char* smem, const float* __restrict__ streams,
    int tok0, int d0, int buf, int ptid) {
    #pragma unroll
    for (int ph = 0; ph < 2; ph++) {
        int idx0  = ptid + (2 * ph) * N_PROD_T;
        int idx1  = idx0 + N_PROD_T;
        int tk0i  = idx0 >> 4, sl0 = idx0 & 15;
        int tk1i  = idx1 >> 4, sl1 = idx1 & 15;
        const float4* s0 = reinterpret_cast<const float4*>(streams)
            + ((size_t)(tok0 + tk0i) * N_STREAMS * D_MODEL + d0) / 4 + sl0;
        const float4* s1 = reinterpret_cast<const float4*>(streams)
            + ((size_t)(tok0 + tk1i) * N_STREAMS * D_MODEL + d0) / 4 + sl1;
        float4 v[N_STREAMS], u[N_STREAMS];
        #pragma unroll
        for (int n = 0; n < N_STREAMS; n++) {
            v[n] = s0[n * (D_MODEL / 4)];
            u[n] = s1[n * (D_MODEL / 4)];
        }
        #pragma unroll
        for (int s = N_STREAMS / 2; s > 0; s >>= 1)
            #pragma unroll
            for (int n = 0; n < s; n++) {
                v[n].x += v[n+s].x; v[n].y += v[n+s].y;
                v[n].z += v[n+s].z; v[n].w += v[n+s].w;
                u[n].x += u[n+s].x; u[n].y += u[n+s].y;
                u[n].z += u[n+s].z; u[n].w += u[n+s].w;
            }
        float f0[4] = { v[0].x*0.125f, v[0].y*0.125f, v[0].z*0.125f, v[0].w*0.125f };
        float f1[4] = { u[0].x*0.125f, u[0].y*0.125f, u[0].z*0.125f, u[0].w*0.125f };
        __nv_bfloat16 h0[4], l0[4], h1[4], l1[4];
        #pragma unroll
        for (int i = 0; i < 4; i++) {
            h0[i] = __float2bfloat16(f0[i]);
            l0[i] = __float2bfloat16(f0[i] - __bfloat162float(h0[i]));
            h1[i] = __float2bfloat16(f1[i]);
            l1[i] = __float2bfloat16(f1[i] - __bfloat162float(h1[i]));
        }
        *reinterpret_cast<uint2*>(smem + A_OFF(buf,0) + tk0i * PITCH_B + sl0 * 8) =
            *reinterpret_cast<uint2*>(h0);
        *reinterpret_cast<uint2*>(smem + A_OFF(buf,1) + tk0i * PITCH_B + sl0 * 8) =
            *reinterpret_cast<uint2*>(l0);
        *reinterpret_cast<uint2*>(smem + A_OFF(buf,0) + tk1i * PITCH_B + sl1 * 8) =
            *reinterpret_cast<uint2*>(h1);
        *reinterpret_cast<uint2*>(smem + A_OFF(buf,1) + tk1i * PITCH_B + sl1 * 8) =
            *reinterpret_cast<uint2*>(l1);
    }
    // B: 128 rows x 8 quads = 1024; 8 per thread (hi+lo, L2-resident)
    #pragma unroll
    for (int p = 0; p < 8; p++) {
        int idx = ptid + p * N_PROD_T;
        int r = idx >> 3, q = idx & 7;
        size_t gsrc = (size_t)r * D_MODEL + d0 + q * 8;
        *reinterpret_cast<uint4*>(smem + B_OFF(buf,0) + r * PITCH_B + q * 16) =
            *reinterpret_cast<const uint4*>(&g_Whi[gsrc]);
        *reinterpret_cast<uint4*>(smem + B_OFF(buf,1) + r * PITCH_B + q * 16) =
            *reinterpret_cast<const uint4*>(&g_Wlo[gsrc]);
    }
}

__global__ void __launch_bounds__(THREADS, 2)
gomhc_fused_kernel(const float* __restrict__ streams,
                   const float* __restrict__ bias,
                   float* __restrict__ out) {
    extern __shared__ char smem[];
    const int tid  = threadIdx.x;
    const int wid  = tid >> 5;
    const int lane = tid & 31;
    const int tok0 = blockIdx.x * TILE_M;

    if (tid < KPAD)
        *reinterpret_cast<float*>(smem + BIAS_OFF + tid * 4) =
            (tid < N_SKEW) ? bias[tid] : 0.f;

    const bool producer = (wid >= 4);

    // consumer mapping: 4 warps, all 32 rows, wn = wid*32
    const int g  = lane >> 2;
    const int t  = lane & 3;
    const int wn = wid * 32;
    float acc[2][4][4];
    #pragma unroll
    for (int mt = 0; mt < 2; mt++)
        #pragma unroll
        for (int nt = 0; nt < 4; nt++)
            #pragma unroll
            for (int i = 0; i < 4; i++) acc[mt][nt][i] = 0.f;

    if (producer)
        produce_chunk(smem, streams, tok0, 0, 0, tid - 128);
    __syncthreads();

    // =================== main loop ===================
    #pragma unroll 1
    for (int c = 0; c < NC; c++) {
        const int buf = c & 1;

        if (producer) {
            if (c + 1 < NC)
                produce_chunk(smem, streams, tok0, (c + 1) * KC,
                              (c + 1) & 1, tid - 128);
        } else {
            const char* pah = smem + A_OFF(buf, 0);
            const char* pal = smem + A_OFF(buf, 1);
            const char* pbh = smem + B_OFF(buf, 0);
            const char* pbl = smem + B_OFF(buf, 1);
            #pragma unroll
            for (int ks = 0; ks < 4; ks++) {
                const int kb = ks * 16 + 2 * t;
                uint32_t Ah[2][4], Al[2][4];
                #pragma unroll
                for (int mt = 0; mt < 2; mt++) {
                    int r0 = mt * 16 + g;
                    Ah[mt][0] = *reinterpret_cast<const uint32_t*>(pah + (r0    ) * PITCH_B + kb * 2);
                    Ah[mt][1] = *reinterpret_cast<const uint32_t*>(pah + (r0 + 8) * PITCH_B + kb * 2);
                    Ah[mt][2] = *reinterpret_cast<const uint32_t*>(pah + (r0    ) * PITCH_B + (kb + 8) * 2);
                    Ah[mt][3] = *reinterpret_cast<const uint32_t*>(pah + (r0 + 8) * PITCH_B + (kb + 8) * 2);
                    Al[mt][0] = *reinterpret_cast<const uint32_t*>(pal + (r0    ) * PITCH_B + kb * 2);
                    Al[mt][1] = *reinterpret_cast<const uint32_t*>(pal + (r0 + 8) * PITCH_B + kb * 2);
                    Al[mt][2] = *reinterpret_cast<const uint32_t*>(pal + (r0    ) * PITCH_B + (kb + 8) * 2);
                    Al[mt][3] = *reinterpret_cast<const uint32_t*>(pal + (r0 + 8) * PITCH_B + (kb + 8) * 2);
                }
                #pragma unroll
                for (int nt = 0; nt < 4; nt++) {
                    int n0 = wn + nt * 8 + g;
                    uint32_t bh0 = *reinterpret_cast<const uint32_t*>(pbh + n0 * PITCH_B + kb * 2);
                    uint32_t bh1 = *reinterpret_cast<const uint32_t*>(pbh + n0 * PITCH_B + (kb + 8) * 2);
                    uint32_t bl0 = *reinterpret_cast<const uint32_t*>(pbl + n0 * PITCH_B + kb * 2);
                    uint32_t bl1 = *reinterpret_cast<const uint32_t*>(pbl + n0 * PITCH_B + (kb + 8) * 2);
                    #pragma unroll
                    for (int mt = 0; mt < 2; mt++) {
                        mma16816(acc[mt][nt], Ah[mt], bh0, bh1);
                        mma16816(acc[mt][nt], Ah[mt], bl0, bl1);
                        mma16816(acc[mt][nt], Al[mt], bh0, bh1);
                    }
                }
            }
        }
        __syncthreads();
    }

    // =================== epilogue: z -> smem (alias over A region) ===================
    float* zs = reinterpret_cast<float*>(smem);    // [32][128] = 16 KB
    if (!producer) {
        #pragma unroll
        for (int mt = 0; mt < 2; mt++)
            #pragma unroll
            for (int nt = 0; nt < 4; nt++) {
                int row = mt * 16 + g;
                int col = wn + nt * 8 + 2 * t;
                *reinterpret_cast<float2*>(&zs[row * KPAD + col]) =
                    make_float2(acc[mt][nt][0], acc[mt][nt][1]);
                *reinterpret_cast<float2*>(&zs[(row + 8) * KPAD + col]) =
                    make_float2(acc[mt][nt][2], acc[mt][nt][3]);
            }
    }
    __syncthreads();

    // =================== solve: 8 warps x 2 passes x 2 tokens = 32 ===================
    {
        const float* bs = reinterpret_cast<const float*>(smem + BIAS_OFF);
        const int half = lane >> 4;
        const int r    = lane & 15;
        const unsigned mask = 0xffffffffu;

        #pragma unroll 1
        for (int pass = 0; pass < 2; pass++) {
            const int tk = wid * 4 + pass * 2 + half;   // 0..31
            const float* zt = zs + tk * KPAD;

            float m[32];
            #pragma unroll
            for (int cc = 0; cc < NS; cc++) {
                float a = 0.f;
                if (cc > r) {
                    int u = (r * (31 - r)) / 2 + (cc - r - 1);
                    a = zt[u] + bs[u];
                } else if (cc < r) {
                    int u = (cc * (31 - cc)) / 2 + (r - cc - 1);
                    a = -(zt[u] + bs[u]);
                }
                float diag = (cc == r) ? 1.f : 0.f;
                m[cc]      = diag + a;
                m[16 + cc] = diag - a;
            }

            #pragma unroll
            for (int i = 0; i < NS; i++) {
                const int src = i + (half << 4);
                float pivi = __shfl_sync(mask, m[i], src);
                float rp = 1.0f / pivi;
                float cf = (r == i) ? (1.0f - rp) : m[i] * rp;
                #pragma unroll
                for (int k = 0; k < 32; k++) {
                    float pk = __shfl_sync(mask, m[k], src);
                    m[k] = fmaf(-cf, pk, m[k]);
                }
            }

            float hq[8];
            #pragma unroll
            for (int q = 0; q < 8; q++) {
                float q0 = m[16 + 2 * q], q1 = m[16 + 2 * q + 1];
                hq[q] = q0 * q0 + q1 * q1;
            }
            #pragma unroll
            for (int q = 0; q < 8; q++)
                hq[q] += __shfl_xor_sync(mask, hq[q], 1);

            if (!(r & 1)) {
                const int tok = tok0 + tk;
                float* o = out + (size_t)tok * 64 + (r >> 1) * 8;
                #pragma unroll
                for (int q = 0; q < 8; q++) o[q] = 0.5f * hq[q];
            }
        }
    }
}

// ---------------- launch ----------------
extern "C" void kernel_launch(void* const* d_in, const int* in_sizes, int n_in,
                              void* d_out, int out_size) {
    const float* streams = (const float*)d_in[0];
    const float* W       = (const float*)d_in[1];
    const float* b       = (const float*)d_in[2];
    float* out = (float*)d_out;

    prep_wt_kernel<<<(KPAD * D_MODEL) / 256, 256>>>(W);

    cudaFuncSetAttribute(gomhc_fused_kernel,
                         cudaFuncAttributeMaxDynamicSharedMemorySize, SMEM_TOTAL);
    gomhc_fused_kernel<<<M_TILES, THREADS, SMEM_TOTAL>>>(streams, b, out);
}

// round 14
// speedup vs baseline: 1.3860x; 1.0077x over previous
#include <cuda_runtime.h>
#include <cuda_bf16.h>
#include <cstdint>

// ---------------- problem constants ----------------
#define N_STREAMS 8
#define D_MODEL   2048
#define NS        16
#define N_SKEW    120
#define KPAD      128
#define TOKENS    8192

#define TILE_M    32
#define M_TILES   (TOKENS / TILE_M)    // 256
#define KC        64                   // d per chunk
#define NC        (D_MODEL / KC)       // 32 chunks
#define PITCH_B   144                  // row pitch bytes (72 bf16)

#define THREADS   256
#define N_PROD_T  128                  // producer threads (warps 4..7)

// smem layout (bytes)
#define A_OFF(buf, hl) (((buf) * 2 + (hl)) * 4608)           // 32 rows * 144
#define B_BASE 18432
#define B_OFF(buf, hl) (B_BASE + ((buf) * 2 + (hl)) * 18432) // 128 rows * 144
#define BIAS_OFF (B_BASE + 73728)                            // = 92160
#define SMEM_TOTAL (BIAS_OFF + 512)                          // 92672

// named barriers: FULL[buf] = 1+buf, EMPTY[buf] = 3+buf
#define BAR_SYNC(id)   asm volatile("bar.sync %0, 256;"   :: "r"(id) : "memory")
#define BAR_ARRIVE(id) asm volatile("bar.arrive %0, 256;" :: "r"(id) : "memory")

// ---------------- device scratch ----------------
__device__ __nv_bfloat16 g_Whi[KPAD * D_MODEL];   // 512 KB
__device__ __nv_bfloat16 g_Wlo[KPAD * D_MODEL];   // 512 KB

// ---------------- K0: W -> bf16 hi/lo (padded to 128 rows) ----------------
__global__ void prep_wt_kernel(const float* __restrict__ W) {
    int id = blockIdx.x * 256 + threadIdx.x;
    int k = id >> 11, d = id & (D_MODEL - 1);
    float v = (k < N_SKEW) ? W[k * D_MODEL + d] : 0.f;
    __nv_bfloat16 hi = __float2bfloat16(v);
    __nv_bfloat16 lo = __float2bfloat16(v - __bfloat162float(hi));
    g_Whi[id] = hi;
    g_Wlo[id] = lo;
}

// ---------------- fused kernel ----------------
__device__ __forceinline__ void mma16816(float c[4], const uint32_t a[4],
                                         uint32_t b0, uint32_t b1) {
    asm volatile(
        "mma.sync.aligned.m16n8k16.row.col.f32.bf16.bf16.f32 "
        "{%0,%1,%2,%3}, {%4,%5,%6,%7}, {%8,%9}, {%0,%1,%2,%3};"
        : "+f"(c[0]), "+f"(c[1]), "+f"(c[2]), "+f"(c[3])
        : "r"(a[0]), "r"(a[1]), "r"(a[2]), "r"(a[3]), "r"(b0), "r"(b1));
}

// producer: stage one chunk into buffer buf; ptid in [0,128)
__device__ __forceinline__ void produce_chunk(
    char* smem, const float* __restrict__ streams,
    int tok0, int d0, int buf, int ptid) {
    #pragma unroll
    for (int ph = 0; ph < 2; ph++) {
        int idx0  = ptid + (2 * ph) * N_PROD_T;
        int idx1  = idx0 + N_PROD_T;
        int tk0i  = idx0 >> 4, sl0 = idx0 & 15;
        int tk1i  = idx1 >> 4, sl1 = idx1 & 15;
        const float4* s0 = reinterpret_cast<const float4*>(streams)
            + ((size_t)(tok0 + tk0i) * N_STREAMS * D_MODEL + d0) / 4 + sl0;
        const float4* s1 = reinterpret_cast<const float4*>(streams)
            + ((size_t)(tok0 + tk1i) * N_STREAMS * D_MODEL + d0) / 4 + sl1;
        float4 v[N_STREAMS], u[N_STREAMS];
        #pragma unroll
        for (int n = 0; n < N_STREAMS; n++) {
            v[n] = s0[n * (D_MODEL / 4)];
            u[n] = s1[n * (D_MODEL / 4)];
        }
        #pragma unroll
        for (int s = N_STREAMS / 2; s > 0; s >>= 1)
            #pragma unroll
            for (int n = 0; n < s; n++) {
                v[n].x += v[n+s].x; v[n].y += v[n+s].y;
                v[n].z += v[n+s].z; v[n].w += v[n+s].w;
                u[n].x += u[n+s].x; u[n].y += u[n+s].y;
                u[n].z += u[n+s].z; u[n].w += u[n+s].w;
            }
        float f0[4] = { v[0].x*0.125f, v[0].y*0.125f, v[0].z*0.125f, v[0].w*0.125f };
        float f1[4] = { u[0].x*0.125f, u[0].y*0.125f, u[0].z*0.125f, u[0].w*0.125f };
        __nv_bfloat16 h0[4], l0[4], h1[4], l1[4];
        #pragma unroll
        for (int i = 0; i < 4; i++) {
            h0[i] = __float2bfloat16(f0[i]);
            l0[i] = __float2bfloat16(f0[i] - __bfloat162float(h0[i]));
            h1[i] = __float2bfloat16(f1[i]);
            l1[i] = __float2bfloat16(f1[i] - __bfloat162float(h1[i]));
        }
        *reinterpret_cast<uint2*>(smem + A_OFF(buf,0) + tk0i * PITCH_B + sl0 * 8) =
            *reinterpret_cast<uint2*>(h0);
        *reinterpret_cast<uint2*>(smem + A_OFF(buf,1) + tk0i * PITCH_B + sl0 * 8) =
            *reinterpret_cast<uint2*>(l0);
        *reinterpret_cast<uint2*>(smem + A_OFF(buf,0) + tk1i * PITCH_B + sl1 * 8) =
            *reinterpret_cast<uint2*>(h1);
        *reinterpret_cast<uint2*>(smem + A_OFF(buf,1) + tk1i * PITCH_B + sl1 * 8) =
            *reinterpret_cast<uint2*>(l1);
    }
    // B: 128 rows x 8 quads = 1024; 8 per thread (hi+lo, L2-resident)
    #pragma unroll
    for (int p = 0; p < 8; p++) {
        int idx = ptid + p * N_PROD_T;
        int r = idx >> 3, q = idx & 7;
        size_t gsrc = (size_t)r * D_MODEL + d0 + q * 8;
        *reinterpret_cast<uint4*>(smem + B_OFF(buf,0) + r * PITCH_B + q * 16) =
            *reinterpret_cast<const uint4*>(&g_Whi[gsrc]);
        *reinterpret_cast<uint4*>(smem + B_OFF(buf,1) + r * PITCH_B + q * 16) =
            *reinterpret_cast<const uint4*>(&g_Wlo[gsrc]);
    }
}

__global__ void __launch_bounds__(THREADS, 2)
gomhc_fused_kernel(const float* __restrict__ streams,
                   const float* __restrict__ bias,
                   float* __restrict__ out) {
    extern __shared__ char smem[];
    const int tid  = threadIdx.x;
    const int wid  = tid >> 5;
    const int lane = tid & 31;
    const int tok0 = blockIdx.x * TILE_M;

    if (tid < KPAD)
        *reinterpret_cast<float*>(smem + BIAS_OFF + tid * 4) =
            (tid < N_SKEW) ? bias[tid] : 0.f;

    const bool producer = (wid >= 4);

    if (producer) {
        // ---- producer: run ahead, gated only by buffer emptiness ----
        const int ptid = tid - 128;
        produce_chunk(smem, streams, tok0, 0 * KC, 0, ptid);
        BAR_ARRIVE(1);                     // FULL[0]
        produce_chunk(smem, streams, tok0, 1 * KC, 1, ptid);
        BAR_ARRIVE(2);                     // FULL[1]
        #pragma unroll 1
        for (int c = 2; c < NC; c++) {
            BAR_SYNC(3 + (c & 1));         // EMPTY[buf]: consumers done with c-2
            produce_chunk(smem, streams, tok0, c * KC, c & 1, ptid);
            BAR_ARRIVE(1 + (c & 1));       // FULL[buf]
        }
    } else {
        // ---- consumer ----
        const int g  = lane >> 2;
        const int t  = lane & 3;
        const int wn = wid * 32;
        float acc[2][4][4];
        #pragma unroll
        for (int mt = 0; mt < 2; mt++)
            #pragma unroll
            for (int nt = 0; nt < 4; nt++)
                #pragma unroll
                for (int i = 0; i < 4; i++) acc[mt][nt][i] = 0.f;

        #pragma unroll 1
        for (int c = 0; c < NC; c++) {
            const int buf = c & 1;
            BAR_SYNC(1 + buf);             // FULL[buf]
            const char* pah = smem + A_OFF(buf, 0);
            const char* pal = smem + A_OFF(buf, 1);
            const char* pbh = smem + B_OFF(buf, 0);
            const char* pbl = smem + B_OFF(buf, 1);
            #pragma unroll
            for (int ks = 0; ks < 4; ks++) {
                const int kb = ks * 16 + 2 * t;
                uint32_t Ah[2][4], Al[2][4];
                #pragma unroll
                for (int mt = 0; mt < 2; mt++) {
                    int r0 = mt * 16 + g;
                    Ah[mt][0] = *reinterpret_cast<const uint32_t*>(pah + (r0    ) * PITCH_B + kb * 2);
                    Ah[mt][1] = *reinterpret_cast<const uint32_t*>(pah + (r0 + 8) * PITCH_B + kb * 2);
                    Ah[mt][2] = *reinterpret_cast<const uint32_t*>(pah + (r0    ) * PITCH_B + (kb + 8) * 2);
                    Ah[mt][3] = *reinterpret_cast<const uint32_t*>(pah + (r0 + 8) * PITCH_B + (kb + 8) * 2);
                    Al[mt][0] = *reinterpret_cast<const uint32_t*>(pal + (r0    ) * PITCH_B + kb * 2);
                    Al[mt][1] = *reinterpret_cast<const uint32_t*>(pal + (r0 + 8) * PITCH_B + kb * 2);
                    Al[mt][2] = *reinterpret_cast<const uint32_t*>(pal + (r0    ) * PITCH_B + (kb + 8) * 2);
                    Al[mt][3] = *reinterpret_cast<const uint32_t*>(pal + (r0 + 8) * PITCH_B + (kb + 8) * 2);
                }
                #pragma unroll
                for (int nt = 0; nt < 4; nt++) {
                    int n0 = wn + nt * 8 + g;
                    uint32_t bh0 = *reinterpret_cast<const uint32_t*>(pbh + n0 * PITCH_B + kb * 2);
                    uint32_t bh1 = *reinterpret_cast<const uint32_t*>(pbh + n0 * PITCH_B + (kb + 8) * 2);
                    uint32_t bl0 = *reinterpret_cast<const uint32_t*>(pbl + n0 * PITCH_B + kb * 2);
                    uint32_t bl1 = *reinterpret_cast<const uint32_t*>(pbl + n0 * PITCH_B + (kb + 8) * 2);
                    #pragma unroll
                    for (int mt = 0; mt < 2; mt++) {
                        mma16816(acc[mt][nt], Ah[mt], bh0, bh1);
                        mma16816(acc[mt][nt], Ah[mt], bl0, bl1);
                        mma16816(acc[mt][nt], Al[mt], bh0, bh1);
                    }
                }
            }
            BAR_ARRIVE(3 + buf);           // EMPTY[buf]
        }

        // stash acc in registers until the global sync below
        __syncthreads();                   // join producers (they're done)

        // epilogue: z -> smem (alias over A region)
        float* zs = reinterpret_cast<float*>(smem);    // [32][128]
        #pragma unroll
        for (int mt = 0; mt < 2; mt++)
            #pragma unroll
            for (int nt = 0; nt < 4; nt++) {
                int row = mt * 16 + g;
                int col = wn + nt * 8 + 2 * t;
                *reinterpret_cast<float2*>(&zs[row * KPAD + col]) =
                    make_float2(acc[mt][nt][0], acc[mt][nt][1]);
                *reinterpret_cast<float2*>(&zs[(row + 8) * KPAD + col]) =
                    make_float2(acc[mt][nt][2], acc[mt][nt][3]);
            }
    }

    if (producer) __syncthreads();          // matching barrier-0 for producers
    __syncthreads();                        // zs visible to all

    // =================== solve: 8 warps x 2 passes x 2 tokens = 32 ===================
    {
        float* zs = reinterpret_cast<float*>(smem);
        const float* bs = reinterpret_cast<const float*>(smem + BIAS_OFF);
        const int half = lane >> 4;
        const int r    = lane & 15;
        const unsigned mask = 0xffffffffu;

        #pragma unroll 1
        for (int pass = 0; pass < 2; pass++) {
            const int tk = wid * 4 + pass * 2 + half;   // 0..31
            const float* zt = zs + tk * KPAD;

            float m[32];
            #pragma unroll
            for (int cc = 0; cc < NS; cc++) {
                float a = 0.f;
                if (cc > r) {
                    int u = (r * (31 - r)) / 2 + (cc - r - 1);
                    a = zt[u] + bs[u];
                } else if (cc < r) {
                    int u = (cc * (31 - cc)) / 2 + (r - cc - 1);
                    a = -(zt[u] + bs[u]);
                }
                float diag = (cc == r) ? 1.f : 0.f;
                m[cc]      = diag + a;
                m[16 + cc] = diag - a;
            }

            #pragma unroll
            for (int i = 0; i < NS; i++) {
                const int src = i + (half << 4);
                float pivi = __shfl_sync(mask, m[i], src);
                float rp = 1.0f / pivi;
                float cf = (r == i) ? (1.0f - rp) : m[i] * rp;
                #pragma unroll
                for (int k = 0; k < 32; k++) {
                    float pk = __shfl_sync(mask, m[k], src);
                    m[k] = fmaf(-cf, pk, m[k]);
                }
            }

            float hq[8];
            #pragma unroll
            for (int q = 0; q < 8; q++) {
                float q0 = m[16 + 2 * q], q1 = m[16 + 2 * q + 1];
                hq[q] = q0 * q0 + q1 * q1;
            }
            #pragma unroll
            for (int q = 0; q < 8; q++)
                hq[q] += __shfl_xor_sync(mask, hq[q], 1);

            if (!(r & 1)) {
                const int tok = tok0 + tk;
                float* o = out + (size_t)tok * 64 + (r >> 1) * 8;
                #pragma unroll
                for (int q = 0; q < 8; q++) o[q] = 0.5f * hq[q];
            }
        }
    }
}

// ---------------- launch ----------------
extern "C" void kernel_launch(void* const* d_in, const int* in_sizes, int n_in,
                              void* d_out, int out_size) {
    const float* streams = (const float*)d_in[0];
    const float* W       = (const float*)d_in[1];
    const float* b       = (const float*)d_in[2];
    float* out = (float*)d_out;

    prep_wt_kernel<<<(KPAD * D_MODEL) / 256, 256>>>(W);

    cudaFuncSetAttribute(gomhc_fused_kernel,
                         cudaFuncAttributeMaxDynamicSharedMemorySize, SMEM_TOTAL);
    gomhc_fused_kernel<<<M_TILES, THREADS, SMEM_TOTAL>>>(streams, b, out);
}